// round 8
// baseline (speedup 1.0000x reference)
#include <cuda_runtime.h>

#define N_NODES 100000
#define N_EDGES 3200000
#define EPS_F 1e-6f
#define EDGE_BLOCKS 1480
#define EDGE_THREADS 256

// Scratch (no allocations allowed).
__device__ float    g_node_sum[N_NODES];
__device__ double   g_acc[5];            // p0, p1, p0^2, p1^2 sums
__device__ unsigned g_done;

__device__ __forceinline__ float warp_sum(float v) {
    #pragma unroll
    for (int o = 16; o; o >>= 1) v += __shfl_xor_sync(0xffffffffu, v, o);
    return v;
}

__global__ void init_kernel() {
    int i = blockIdx.x * blockDim.x + threadIdx.x;
    if (i < N_NODES) g_node_sum[i] = 0.0f;
    if (i < 5)       g_acc[i] = 0.0;
    if (i == 5)      g_done = 0u;
}

// One pass over edges (exact R5 body: __restrict__ gather from node_features):
// scatter currents, accumulate variance moments. Last block to finish reduces
// node sums and finalizes the scalar.
__global__ void __launch_bounds__(EDGE_THREADS) edge_kernel(
    const float* __restrict__ node_features,
    const int*   __restrict__ edge_index,
    const float* __restrict__ edge_logits,
    const float2* __restrict__ edge_params,
    float* __restrict__ out)
{
    float s0 = 0.f, s1 = 0.f, q0 = 0.f, q1 = 0.f;

    const int stride = gridDim.x * blockDim.x;
    for (int e = blockIdx.x * blockDim.x + threadIdx.x; e < N_EDGES; e += stride) {
        int src = edge_index[e];
        int dst = edge_index[N_EDGES + e];
        float2 p  = edge_params[e];
        float  lg = edge_logits[e];

        float prob = 1.0f / (1.0f + __expf(-lg));

        float vs = node_features[src * 4];   // column 0, row stride 4
        float vd = node_features[dst * 4];
        float vdiff = fabsf(vs - vd);
        float cur = vdiff / (p.x + p.y + EPS_F) * prob;

        atomicAdd(&g_node_sum[dst],  cur);
        atomicAdd(&g_node_sum[src], -cur);

        s0 += p.x;  s1 += p.y;
        q0 += p.x * p.x;  q1 += p.y * p.y;
    }

    // Block reduction of the moment accumulators -> double atomics.
    __shared__ float sm[4][8];
    int lane = threadIdx.x & 31;
    int wid  = threadIdx.x >> 5;

    s0 = warp_sum(s0); s1 = warp_sum(s1); q0 = warp_sum(q0); q1 = warp_sum(q1);
    if (lane == 0) { sm[0][wid] = s0; sm[1][wid] = s1; sm[2][wid] = q0; sm[3][wid] = q1; }
    __syncthreads();
    if (wid == 0) {
        float a = (lane < 8) ? sm[0][lane] : 0.f;
        float b = (lane < 8) ? sm[1][lane] : 0.f;
        float c = (lane < 8) ? sm[2][lane] : 0.f;
        float d = (lane < 8) ? sm[3][lane] : 0.f;
        a = warp_sum(a); b = warp_sum(b); c = warp_sum(c); d = warp_sum(d);
        if (lane == 0) {
            atomicAdd(&g_acc[0], (double)a);
            atomicAdd(&g_acc[1], (double)b);
            atomicAdd(&g_acc[2], (double)c);
            atomicAdd(&g_acc[3], (double)d);
        }
    }

    // Last-block: reduce node_sum^2 and finalize.
    __shared__ unsigned s_is_last;
    __threadfence();
    __syncthreads();
    if (threadIdx.x == 0)
        s_is_last = (atomicAdd(&g_done, 1u) == (unsigned)(gridDim.x - 1));
    __syncthreads();
    if (!s_is_last) return;

    float acc = 0.f;
    for (int i = threadIdx.x; i < N_NODES; i += blockDim.x) {
        float v = g_node_sum[i];
        acc += v * v;
    }
    __shared__ float smn[8];
    acc = warp_sum(acc);
    if (lane == 0) smn[wid] = acc;
    __syncthreads();
    if (wid == 0) {
        float a = (lane < 8) ? smn[lane] : 0.f;
        a = warp_sum(a);
        if (lane == 0) {
            double sum0 = g_acc[0], sum1 = g_acc[1];
            double sq0  = g_acc[2], sq1  = g_acc[3];
            const double E = (double)N_EDGES;
            double var0 = (sq0 - sum0 * sum0 / E) / (E - 1.0);
            double var1 = (sq1 - sum1 * sum1 / E) / (E - 1.0);
            double kvl = 0.5 * (var0 + var1);
            double kcl = (double)a / (double)N_NODES;
            out[0] = (float)(kcl + kvl);
        }
    }
}

extern "C" void kernel_launch(void* const* d_in, const int* in_sizes, int n_in,
                              void* d_out, int out_size)
{
    const float*  node_features = (const float*)d_in[0];
    const int*    edge_index    = (const int*)d_in[1];
    const float*  edge_logits   = (const float*)d_in[2];
    const float2* edge_params   = (const float2*)d_in[3];
    float* out = (float*)d_out;

    (void)in_sizes; (void)n_in; (void)out_size;

    init_kernel<<<(N_NODES + 255) / 256, 256>>>();
    edge_kernel<<<EDGE_BLOCKS, EDGE_THREADS>>>(node_features, edge_index,
                                               edge_logits, edge_params, out);
}

// round 9
// speedup vs baseline: 1.1750x; 1.1750x over previous
#include <cuda_runtime.h>

#define N_NODES 100000
#define N_EDGES 3200000
#define EPS_F 1e-6f
#define EDGE_BLOCKS 1480
#define EDGE_THREADS 256

// Scratch (no allocations allowed).
__device__ float    g_node_sum[N_NODES];
__device__ double   g_acc[5];            // p0, p1, p0^2, p1^2 sums
__device__ unsigned g_done;

__device__ __forceinline__ float warp_sum(float v) {
    #pragma unroll
    for (int o = 16; o; o >>= 1) v += __shfl_xor_sync(0xffffffffu, v, o);
    return v;
}

__global__ void zero_kernel() {
    int i = blockIdx.x * blockDim.x + threadIdx.x;
    if (i < N_NODES) g_node_sum[i] = 0.0f;
    if (i < 5)       g_acc[i] = 0.0;
    if (i == 5)      g_done = 0u;
}

// One pass over edges, 2 edges/thread via vectorized loads. NO tail, no fence,
// no readback of g_node_sum in this kernel: keeps the loop atomics in
// fire-and-forget REDG form (the fused tail in R6-R8 doubled kernel time).
__global__ void __launch_bounds__(EDGE_THREADS) edge_kernel(
    const float* __restrict__ node_features,
    const int*   __restrict__ edge_index,
    const float* __restrict__ edge_logits,
    const float* __restrict__ edge_params)
{
    const int2*   srcs = (const int2*)edge_index;
    const int2*   dsts = (const int2*)(edge_index + N_EDGES);
    const float2* lgs  = (const float2*)edge_logits;
    const float4* pars = (const float4*)edge_params;

    float s0 = 0.f, s1 = 0.f, q0 = 0.f, q1 = 0.f;

    const int stride = gridDim.x * blockDim.x;
    for (int i = blockIdx.x * blockDim.x + threadIdx.x; i < N_EDGES / 2; i += stride) {
        int2   s  = srcs[i];
        int2   d  = dsts[i];
        float2 lg = lgs[i];
        float4 p  = pars[i];

        float prob0 = 1.0f / (1.0f + __expf(-lg.x));
        float prob1 = 1.0f / (1.0f + __expf(-lg.y));

        float v0 = fabsf(node_features[s.x * 4] - node_features[d.x * 4]);
        float v1 = fabsf(node_features[s.y * 4] - node_features[d.y * 4]);

        float cur0 = v0 / (p.x + p.y + EPS_F) * prob0;
        float cur1 = v1 / (p.z + p.w + EPS_F) * prob1;

        atomicAdd(&g_node_sum[d.x],  cur0);
        atomicAdd(&g_node_sum[s.x], -cur0);
        atomicAdd(&g_node_sum[d.y],  cur1);
        atomicAdd(&g_node_sum[s.y], -cur1);

        s0 += p.x + p.z;
        s1 += p.y + p.w;
        q0 += p.x * p.x + p.z * p.z;
        q1 += p.y * p.y + p.w * p.w;
    }

    // Block reduction of the moment accumulators -> double atomics.
    __shared__ float sm[4][8];
    int lane = threadIdx.x & 31;
    int wid  = threadIdx.x >> 5;

    s0 = warp_sum(s0); s1 = warp_sum(s1); q0 = warp_sum(q0); q1 = warp_sum(q1);
    if (lane == 0) { sm[0][wid] = s0; sm[1][wid] = s1; sm[2][wid] = q0; sm[3][wid] = q1; }
    __syncthreads();
    if (wid == 0) {
        float a = (lane < 8) ? sm[0][lane] : 0.f;
        float b = (lane < 8) ? sm[1][lane] : 0.f;
        float c = (lane < 8) ? sm[2][lane] : 0.f;
        float d = (lane < 8) ? sm[3][lane] : 0.f;
        a = warp_sum(a); b = warp_sum(b); c = warp_sum(c); d = warp_sum(d);
        if (lane == 0) {
            atomicAdd(&g_acc[0], (double)a);
            atomicAdd(&g_acc[1], (double)b);
            atomicAdd(&g_acc[2], (double)c);
            atomicAdd(&g_acc[3], (double)d);
        }
    }
}

// Node-sum^2 reduction; the LAST block also finalizes the scalar (this kernel
// has no hot atomic loop, so the fence/counter pattern is harmless here).
__global__ void __launch_bounds__(256) node_kernel(float* __restrict__ out) {
    float acc = 0.f;
    const int stride = gridDim.x * blockDim.x;
    for (int i = blockIdx.x * blockDim.x + threadIdx.x; i < N_NODES; i += stride) {
        float v = g_node_sum[i];
        acc += v * v;
    }
    __shared__ float sm[8];
    int lane = threadIdx.x & 31;
    int wid  = threadIdx.x >> 5;
    acc = warp_sum(acc);
    if (lane == 0) sm[wid] = acc;
    __syncthreads();
    if (wid == 0) {
        float a = (lane < 8) ? sm[lane] : 0.f;
        a = warp_sum(a);
        if (lane == 0) atomicAdd(&g_acc[4], (double)a);
    }

    __shared__ unsigned s_is_last;
    __threadfence();
    __syncthreads();
    if (threadIdx.x == 0)
        s_is_last = (atomicAdd(&g_done, 1u) == (unsigned)(gridDim.x - 1));
    __syncthreads();
    if (!s_is_last) return;

    if (threadIdx.x == 0) {
        double sum0 = g_acc[0], sum1 = g_acc[1];
        double sq0  = g_acc[2], sq1  = g_acc[3];
        double nsq  = g_acc[4];
        const double E = (double)N_EDGES;
        double var0 = (sq0 - sum0 * sum0 / E) / (E - 1.0);
        double var1 = (sq1 - sum1 * sum1 / E) / (E - 1.0);
        double kvl = 0.5 * (var0 + var1);
        double kcl = nsq / (double)N_NODES;
        out[0] = (float)(kcl + kvl);
    }
}

extern "C" void kernel_launch(void* const* d_in, const int* in_sizes, int n_in,
                              void* d_out, int out_size)
{
    const float* node_features = (const float*)d_in[0];
    const int*   edge_index    = (const int*)d_in[1];
    const float* edge_logits   = (const float*)d_in[2];
    const float* edge_params   = (const float*)d_in[3];
    float* out = (float*)d_out;

    (void)in_sizes; (void)n_in; (void)out_size;

    zero_kernel<<<(N_NODES + 255) / 256, 256>>>();
    edge_kernel<<<EDGE_BLOCKS, EDGE_THREADS>>>(node_features, edge_index,
                                               edge_logits, edge_params);
    node_kernel<<<(N_NODES + 255) / 256, 256>>>(out);
}

// round 10
// speedup vs baseline: 1.4797x; 1.2593x over previous
#include <cuda_runtime.h>

#define N_NODES 100000
#define N_EDGES 3200000
#define EPS_F 1e-6f
#define EDGE_BLOCKS 1480
#define EDGE_THREADS 256

// Scratch (no allocations allowed).
__device__ float    g_node_sum[N_NODES];
__device__ double   g_acc[5];            // p0, p1, p0^2, p1^2, node_sum^2
__device__ unsigned g_done;

__device__ __forceinline__ float warp_sum(float v) {
    #pragma unroll
    for (int o = 16; o; o >>= 1) v += __shfl_xor_sync(0xffffffffu, v, o);
    return v;
}

__global__ void zero_kernel() {
    int i = blockIdx.x * blockDim.x + threadIdx.x;
    if (i < N_NODES) g_node_sum[i] = 0.0f;
    if (i < 5)       g_acc[i] = 0.0;
    if (i == 5)      g_done = 0u;
}

// Exact R5 edge kernel: scalar grid-stride loop (1 edge/thread/iter, ~8.4
// iters) — ptxas front-batches the gathers across iterations; atomics stay
// fire-and-forget REDG (no fence / no readback anywhere in this kernel).
__global__ void __launch_bounds__(EDGE_THREADS) edge_kernel(
    const float* __restrict__ node_features,
    const int*   __restrict__ edge_index,
    const float* __restrict__ edge_logits,
    const float2* __restrict__ edge_params)
{
    float s0 = 0.f, s1 = 0.f, q0 = 0.f, q1 = 0.f;

    const int stride = gridDim.x * blockDim.x;
    for (int e = blockIdx.x * blockDim.x + threadIdx.x; e < N_EDGES; e += stride) {
        int src = edge_index[e];
        int dst = edge_index[N_EDGES + e];
        float2 p  = edge_params[e];
        float  lg = edge_logits[e];

        float prob = 1.0f / (1.0f + __expf(-lg));

        float vs = node_features[src * 4];   // column 0, row stride 4
        float vd = node_features[dst * 4];
        float vdiff = fabsf(vs - vd);
        float cur = vdiff / (p.x + p.y + EPS_F) * prob;

        atomicAdd(&g_node_sum[dst],  cur);
        atomicAdd(&g_node_sum[src], -cur);

        s0 += p.x;  s1 += p.y;
        q0 += p.x * p.x;  q1 += p.y * p.y;
    }

    // Block reduction of the moment accumulators -> double atomics.
    __shared__ float sm[4][8];
    int lane = threadIdx.x & 31;
    int wid  = threadIdx.x >> 5;

    s0 = warp_sum(s0); s1 = warp_sum(s1); q0 = warp_sum(q0); q1 = warp_sum(q1);
    if (lane == 0) { sm[0][wid] = s0; sm[1][wid] = s1; sm[2][wid] = q0; sm[3][wid] = q1; }
    __syncthreads();
    if (wid == 0) {
        float a = (lane < 8) ? sm[0][lane] : 0.f;
        float b = (lane < 8) ? sm[1][lane] : 0.f;
        float c = (lane < 8) ? sm[2][lane] : 0.f;
        float d = (lane < 8) ? sm[3][lane] : 0.f;
        a = warp_sum(a); b = warp_sum(b); c = warp_sum(c); d = warp_sum(d);
        if (lane == 0) {
            atomicAdd(&g_acc[0], (double)a);
            atomicAdd(&g_acc[1], (double)b);
            atomicAdd(&g_acc[2], (double)c);
            atomicAdd(&g_acc[3], (double)d);
        }
    }
}

// Node-sum^2 reduction; the LAST block finalizes the scalar (no hot atomic
// loop here, so the fence/counter pattern is harmless in this kernel).
__global__ void __launch_bounds__(256) node_kernel(float* __restrict__ out) {
    float acc = 0.f;
    const int stride = gridDim.x * blockDim.x;
    for (int i = blockIdx.x * blockDim.x + threadIdx.x; i < N_NODES; i += stride) {
        float v = g_node_sum[i];
        acc += v * v;
    }
    __shared__ float sm[8];
    int lane = threadIdx.x & 31;
    int wid  = threadIdx.x >> 5;
    acc = warp_sum(acc);
    if (lane == 0) sm[wid] = acc;
    __syncthreads();
    if (wid == 0) {
        float a = (lane < 8) ? sm[lane] : 0.f;
        a = warp_sum(a);
        if (lane == 0) atomicAdd(&g_acc[4], (double)a);
    }

    __shared__ unsigned s_is_last;
    __threadfence();
    __syncthreads();
    if (threadIdx.x == 0)
        s_is_last = (atomicAdd(&g_done, 1u) == (unsigned)(gridDim.x - 1));
    __syncthreads();
    if (!s_is_last) return;

    if (threadIdx.x == 0) {
        double sum0 = g_acc[0], sum1 = g_acc[1];
        double sq0  = g_acc[2], sq1  = g_acc[3];
        double nsq  = g_acc[4];
        const double E = (double)N_EDGES;
        double var0 = (sq0 - sum0 * sum0 / E) / (E - 1.0);
        double var1 = (sq1 - sum1 * sum1 / E) / (E - 1.0);
        double kvl = 0.5 * (var0 + var1);
        double kcl = nsq / (double)N_NODES;
        out[0] = (float)(kcl + kvl);
    }
}

extern "C" void kernel_launch(void* const* d_in, const int* in_sizes, int n_in,
                              void* d_out, int out_size)
{
    const float*  node_features = (const float*)d_in[0];
    const int*    edge_index    = (const int*)d_in[1];
    const float*  edge_logits   = (const float*)d_in[2];
    const float2* edge_params   = (const float2*)d_in[3];
    float* out = (float*)d_out;

    (void)in_sizes; (void)n_in; (void)out_size;

    zero_kernel<<<(N_NODES + 255) / 256, 256>>>();
    edge_kernel<<<EDGE_BLOCKS, EDGE_THREADS>>>(node_features, edge_index,
                                               edge_logits, edge_params);
    node_kernel<<<(N_NODES + 255) / 256, 256>>>(out);
}

// round 11
// speedup vs baseline: 1.5374x; 1.0390x over previous
#include <cuda_runtime.h>

#define N_NODES 100000
#define N_EDGES 3200000
#define EPS_F 1e-6f
#define EDGE_BLOCKS 1184   // 148 SMs x 8 resident blocks: exactly one wave
#define EDGE_THREADS 256
#define NODE_BLOCKS ((N_NODES + 255) / 256)

// Scratch (no allocations allowed). Zero-initialized at module load; the
// node_final kernel re-zeroes everything it dirties, so every graph replay
// starts from a clean state with no dedicated zeroing launch.
__device__ float    g_node_sum[N_NODES];
__device__ double   g_acc[5];            // p0, p1, p0^2, p1^2, node_sum^2
__device__ unsigned g_done;

__device__ __forceinline__ float warp_sum(float v) {
    #pragma unroll
    for (int o = 16; o; o >>= 1) v += __shfl_xor_sync(0xffffffffu, v, o);
    return v;
}

// Proven R5 edge body: scalar grid-stride loop, fire-and-forget REDG atomics,
// no fence / no readback of g_node_sum anywhere in this kernel.
__global__ void __launch_bounds__(EDGE_THREADS) edge_kernel(
    const float* __restrict__ node_features,
    const int*   __restrict__ edge_index,
    const float* __restrict__ edge_logits,
    const float2* __restrict__ edge_params)
{
    float s0 = 0.f, s1 = 0.f, q0 = 0.f, q1 = 0.f;

    const int stride = gridDim.x * blockDim.x;
    for (int e = blockIdx.x * blockDim.x + threadIdx.x; e < N_EDGES; e += stride) {
        int src = edge_index[e];
        int dst = edge_index[N_EDGES + e];
        float2 p  = edge_params[e];
        float  lg = edge_logits[e];

        float prob = 1.0f / (1.0f + __expf(-lg));

        float vs = node_features[src * 4];   // column 0, row stride 4
        float vd = node_features[dst * 4];
        float vdiff = fabsf(vs - vd);
        float cur = __fdividef(vdiff, p.x + p.y + EPS_F) * prob;

        atomicAdd(&g_node_sum[dst],  cur);
        atomicAdd(&g_node_sum[src], -cur);

        s0 += p.x;  s1 += p.y;
        q0 += p.x * p.x;  q1 += p.y * p.y;
    }

    // Block reduction of the moment accumulators -> double atomics.
    __shared__ float sm[4][8];
    int lane = threadIdx.x & 31;
    int wid  = threadIdx.x >> 5;

    s0 = warp_sum(s0); s1 = warp_sum(s1); q0 = warp_sum(q0); q1 = warp_sum(q1);
    if (lane == 0) { sm[0][wid] = s0; sm[1][wid] = s1; sm[2][wid] = q0; sm[3][wid] = q1; }
    __syncthreads();
    if (wid == 0) {
        float a = (lane < 8) ? sm[0][lane] : 0.f;
        float b = (lane < 8) ? sm[1][lane] : 0.f;
        float c = (lane < 8) ? sm[2][lane] : 0.f;
        float d = (lane < 8) ? sm[3][lane] : 0.f;
        a = warp_sum(a); b = warp_sum(b); c = warp_sum(c); d = warp_sum(d);
        if (lane == 0) {
            atomicAdd(&g_acc[0], (double)a);
            atomicAdd(&g_acc[1], (double)b);
            atomicAdd(&g_acc[2], (double)c);
            atomicAdd(&g_acc[3], (double)d);
        }
    }
}

// Node-sum^2 reduction (one node per thread), zeroing g_node_sum behind
// itself. The LAST block finalizes the scalar and resets g_acc / g_done so
// the next replay starts clean.
__global__ void __launch_bounds__(256) node_final_kernel(float* __restrict__ out) {
    int i = blockIdx.x * blockDim.x + threadIdx.x;
    float acc = 0.f;
    if (i < N_NODES) {
        float v = g_node_sum[i];
        g_node_sum[i] = 0.0f;            // self-clean for next replay
        acc = v * v;
    }

    __shared__ float sm[8];
    int lane = threadIdx.x & 31;
    int wid  = threadIdx.x >> 5;
    acc = warp_sum(acc);
    if (lane == 0) sm[wid] = acc;
    __syncthreads();
    if (wid == 0) {
        float a = (lane < 8) ? sm[lane] : 0.f;
        a = warp_sum(a);
        if (lane == 0) atomicAdd(&g_acc[4], (double)a);
    }

    __shared__ unsigned s_is_last;
    __threadfence();
    __syncthreads();
    if (threadIdx.x == 0)
        s_is_last = (atomicAdd(&g_done, 1u) == (unsigned)(gridDim.x - 1));
    __syncthreads();
    if (!s_is_last) return;

    if (threadIdx.x == 0) {
        double sum0 = g_acc[0], sum1 = g_acc[1];
        double sq0  = g_acc[2], sq1  = g_acc[3];
        double nsq  = g_acc[4];
        const double E = (double)N_EDGES;
        double var0 = (sq0 - sum0 * sum0 / E) / (E - 1.0);
        double var1 = (sq1 - sum1 * sum1 / E) / (E - 1.0);
        double kvl = 0.5 * (var0 + var1);
        double kcl = nsq / (double)N_NODES;
        out[0] = (float)(kcl + kvl);

        // Reset accumulators for the next replay.
        g_acc[0] = 0.0; g_acc[1] = 0.0; g_acc[2] = 0.0;
        g_acc[3] = 0.0; g_acc[4] = 0.0;
        g_done = 0u;
    }
}

extern "C" void kernel_launch(void* const* d_in, const int* in_sizes, int n_in,
                              void* d_out, int out_size)
{
    const float*  node_features = (const float*)d_in[0];
    const int*    edge_index    = (const int*)d_in[1];
    const float*  edge_logits   = (const float*)d_in[2];
    const float2* edge_params   = (const float2*)d_in[3];
    float* out = (float*)d_out;

    (void)in_sizes; (void)n_in; (void)out_size;

    edge_kernel<<<EDGE_BLOCKS, EDGE_THREADS>>>(node_features, edge_index,
                                               edge_logits, edge_params);
    node_final_kernel<<<NODE_BLOCKS, 256>>>(out);
}